// round 2
// baseline (speedup 1.0000x reference)
#include <cuda_runtime.h>
#include <math.h>

#define FULL 0xffffffffu
#define LOG2E 1.4426950408889634f
#define LN2   0.6931471805599453f

// Precomputed log_softmax(W_m, axis=0) * LOG2E  [32,32,32], and a0 [32]
__device__ float g_wl2[32 * 32 * 32];
__device__ float g_a0[32];

__device__ __forceinline__ float ex2f(float x) {
    float y; asm("ex2.approx.f32 %0, %1;" : "=f"(y) : "f"(x)); return y;
}
__device__ __forceinline__ float lg2f(float x) {
    float y; asm("lg2.approx.f32 %0, %1;" : "=f"(y) : "f"(x)); return y;
}

// ---------------------------------------------------------------------------
// Prep: thread t = (m, k') computes log_softmax over k of W[m, k, k'] (axis=0),
// scaled by LOG2E. Threads 0..31 also compute a0 (plain log units).
// ---------------------------------------------------------------------------
__global__ void tt_prep_kernel(const float* __restrict__ W,
                               const float* __restrict__ wk0) {
    int t = threadIdx.x;
    int m = t >> 5, kp = t & 31;

    float v[32];
    float mx = -INFINITY;
#pragma unroll
    for (int k = 0; k < 32; k++) {
        v[k] = W[m * 1024 + k * 32 + kp];
        mx = fmaxf(mx, v[k]);
    }
    float s = 0.f;
#pragma unroll
    for (int k = 0; k < 32; k++) s += expf(v[k] - mx);
    float lse = mx + logf(s);
#pragma unroll
    for (int k = 0; k < 32; k++)
        g_wl2[m * 1024 + k * 32 + kp] = (v[k] - lse) * LOG2E;

    if (t < 32) {
        float m2 = -INFINITY;
#pragma unroll
        for (int k = 0; k < 32; k++) m2 = fmaxf(m2, wk0[k]);
        float s2 = 0.f;
#pragma unroll
        for (int k = 0; k < 32; k++) s2 += expf(wk0[k] - m2);
        g_a0[t] = wk0[t] - (m2 + logf(s2));
    }
}

// ---------------------------------------------------------------------------
// Main: 256 threads (8 warps) per CTA, 4 CTAs/SM target. Each warp handles
// 2 samples (A, B); lane = output column k'. One-pass logsumexp per step:
// offset = warp-max of a (valid since log_softmax(W) <= 0 keeps args bounded).
// wl2 is read through L1 (__ldg, 128 KB resident); L is streamed with __ldcs
// (evict-first) so it never evicts wl2.
// ---------------------------------------------------------------------------
__global__ void __launch_bounds__(256, 4)
tt_main_kernel(const float* __restrict__ L, float* __restrict__ out) {
    const int warp = threadIdx.x >> 5;
    const int lane = threadIdx.x & 31;
    const int n0 = (blockIdx.x * 8 + warp) * 2;

    const float* LA = L + (size_t)n0 * 32768 + lane;
    const float* LB = LA + 32768;
    const float* wp = g_wl2 + lane;

    float aA = g_a0[lane];
    float aB = aA;

#pragma unroll 1
    for (int m = 0; m < 32; m++) {
        // Warp-wide max of a for each sample (stability offset).
        float mxA = aA, mxB = aB;
#pragma unroll
        for (int off = 16; off; off >>= 1) {
            mxA = fmaxf(mxA, __shfl_xor_sync(FULL, mxA, off));
            mxB = fmaxf(mxB, __shfl_xor_sync(FULL, mxB, off));
        }
        const float tA = (aA - mxA) * LOG2E;
        const float tB = (aB - mxB) * LOG2E;

        const float* lA = LA + m * 1024;
        const float* lB = LB + m * 1024;
        const float* w  = wp + m * 1024;

        float accA0 = 0.f, accA1 = 0.f, accB0 = 0.f, accB1 = 0.f;
#pragma unroll
        for (int k = 0; k < 32; k += 2) {
            float w2a = __ldg(w + k * 32);
            float w2b = __ldg(w + (k + 1) * 32);
            float lA0 = __ldcs(lA + k * 32);
            float lA1 = __ldcs(lA + (k + 1) * 32);
            float lB0 = __ldcs(lB + k * 32);
            float lB1 = __ldcs(lB + (k + 1) * 32);
            float tA0 = __shfl_sync(FULL, tA, k);
            float tA1 = __shfl_sync(FULL, tA, k + 1);
            float tB0 = __shfl_sync(FULL, tB, k);
            float tB1 = __shfl_sync(FULL, tB, k + 1);
            accA0 += ex2f(fmaf(lA0, LOG2E, tA0 + w2a));
            accA1 += ex2f(fmaf(lA1, LOG2E, tA1 + w2b));
            accB0 += ex2f(fmaf(lB0, LOG2E, tB0 + w2a));
            accB1 += ex2f(fmaf(lB1, LOG2E, tB1 + w2b));
        }
        aA = fmaf(lg2f(accA0 + accA1), LN2, mxA);
        aB = fmaf(lg2f(accB0 + accB1), LN2, mxB);
    }

    // Final logsumexp across the 32 lanes (columns) for each sample.
    float mA = aA, mB = aB;
#pragma unroll
    for (int off = 16; off; off >>= 1) {
        mA = fmaxf(mA, __shfl_xor_sync(FULL, mA, off));
        mB = fmaxf(mB, __shfl_xor_sync(FULL, mB, off));
    }
    float eA = ex2f((aA - mA) * LOG2E);
    float eB = ex2f((aB - mB) * LOG2E);
#pragma unroll
    for (int off = 16; off; off >>= 1) {
        eA += __shfl_xor_sync(FULL, eA, off);
        eB += __shfl_xor_sync(FULL, eB, off);
    }
    if (lane == 0) {
        out[n0]     = fmaf(lg2f(eA), LN2, mA);
        out[n0 + 1] = fmaf(lg2f(eB), LN2, mB);
    }
}

// ---------------------------------------------------------------------------
// Launch contract
// ---------------------------------------------------------------------------
extern "C" void kernel_launch(void* const* d_in, const int* in_sizes, int n_in,
                              void* d_out, int out_size) {
    const float* L   = (const float*)d_in[0];   // [8192, 32, 32, 32]
    const float* wk0 = (const float*)d_in[1];   // [1, 32]
    const float* W   = (const float*)d_in[2];   // [32, 32, 32]
    float* out = (float*)d_out;                 // [8192]

    (void)in_sizes; (void)n_in; (void)out_size;

    tt_prep_kernel<<<1, 1024>>>(W, wk0);
    // 8192 samples / 2 per warp / 8 warps per CTA = 512 CTAs
    tt_main_kernel<<<512, 256>>>(L, out);
}

// round 3
// speedup vs baseline: 1.2032x; 1.2032x over previous
#include <cuda_runtime.h>
#include <math.h>

#define FULL 0xffffffffu
#define LOG2E 1.4426950408889634f
#define LN2   0.6931471805599453f

// Precomputed log_softmax(W_m, axis=0) * LOG2E  [32,32,32], and a0 [32]
__device__ float g_wl2[32 * 32 * 32];
__device__ float g_a0[32];

__device__ __forceinline__ float ex2f(float x) {
    float y; asm("ex2.approx.f32 %0, %1;" : "=f"(y) : "f"(x)); return y;
}
__device__ __forceinline__ float lg2f(float x) {
    float y; asm("lg2.approx.f32 %0, %1;" : "=f"(y) : "f"(x)); return y;
}
__device__ __forceinline__ float4 ldcs4(const float4* p) {
    float4 v;
    asm volatile("ld.global.cs.v4.f32 {%0,%1,%2,%3}, [%4];"
                 : "=f"(v.x), "=f"(v.y), "=f"(v.z), "=f"(v.w) : "l"(p));
    return v;
}

// ---------------------------------------------------------------------------
// Prep: thread t = (m, k') computes log_softmax over k of W[m, k, k'] (axis=0),
// scaled by LOG2E. Threads 0..31 also compute a0 (plain log units).
// ---------------------------------------------------------------------------
__global__ void tt_prep_kernel(const float* __restrict__ W,
                               const float* __restrict__ wk0) {
    int t = threadIdx.x;
    int m = t >> 5, kp = t & 31;

    float v[32];
    float mx = -INFINITY;
#pragma unroll
    for (int k = 0; k < 32; k++) {
        v[k] = W[m * 1024 + k * 32 + kp];
        mx = fmaxf(mx, v[k]);
    }
    float s = 0.f;
#pragma unroll
    for (int k = 0; k < 32; k++) s += expf(v[k] - mx);
    float lse = mx + logf(s);
#pragma unroll
    for (int k = 0; k < 32; k++)
        g_wl2[m * 1024 + k * 32 + kp] = (v[k] - lse) * LOG2E;

    if (t < 32) {
        float m2 = -INFINITY;
#pragma unroll
        for (int k = 0; k < 32; k++) m2 = fmaxf(m2, wk0[k]);
        float s2 = 0.f;
#pragma unroll
        for (int k = 0; k < 32; k++) s2 += expf(wk0[k] - m2);
        g_a0[t] = wk0[t] - (m2 + logf(s2));
    }
}

// ---------------------------------------------------------------------------
// Main: 8 warps/CTA, each warp handles 2 samples (A, B), ALL loads float4.
// Lane i owns rows r == i/8 (mod 4) and k' columns [4(i%8), 4(i%8)+3].
// float4 index for (m, block b): m*256 + b*32 + lane  (fully coalesced 128B).
// acc[k'] = sum_k e^{a_k - mx} * 2^{wls*LOG2E + l*LOG2E}  — one-pass stable
// since log_softmax(W) <= 0 bounds every term by e^{max l} (~e^6).
// ---------------------------------------------------------------------------
__global__ void __launch_bounds__(256, 4)
tt_main_kernel(const float* __restrict__ L, float* __restrict__ out) {
    const int warp = threadIdx.x >> 5;
    const int lane = threadIdx.x & 31;
    const int n0 = (blockIdx.x * 8 + warp) * 2;
    const int rsub = lane >> 3;  // row-within-block

    const float4* LA = (const float4*)L + (size_t)n0 * 8192 + lane;
    const float4* LB = LA + 8192;
    const float4* W4 = (const float4*)g_wl2 + lane;

    float aA = g_a0[lane];
    float aB = aA;

#pragma unroll 1
    for (int m = 0; m < 32; m++) {
        // Stability offset: warp-max of a per sample.
        float mxA = aA, mxB = aB;
#pragma unroll
        for (int off = 16; off; off >>= 1) {
            mxA = fmaxf(mxA, __shfl_xor_sync(FULL, mxA, off));
            mxB = fmaxf(mxB, __shfl_xor_sync(FULL, mxB, off));
        }
        const float tA = (aA - mxA) * LOG2E;  // log2 units
        const float tB = (aB - mxB) * LOG2E;

        const float4* lA = LA + m * 256;
        const float4* lB = LB + m * 256;
        const float4* w  = W4 + m * 256;

        float4 accA = make_float4(0.f, 0.f, 0.f, 0.f);
        float4 accB = make_float4(0.f, 0.f, 0.f, 0.f);

#pragma unroll
        for (int b = 0; b < 8; b++) {
            float4 w4  = __ldg(w + b * 32);
            float4 l4A = ldcs4(lA + b * 32);
            float4 l4B = ldcs4(lB + b * 32);
            int row = 4 * b + rsub;
            float pA = ex2f(__shfl_sync(FULL, tA, row));  // e^{a_row - mx}
            float pB = ex2f(__shfl_sync(FULL, tB, row));

            accA.x = fmaf(pA, ex2f(fmaf(l4A.x, LOG2E, w4.x)), accA.x);
            accA.y = fmaf(pA, ex2f(fmaf(l4A.y, LOG2E, w4.y)), accA.y);
            accA.z = fmaf(pA, ex2f(fmaf(l4A.z, LOG2E, w4.z)), accA.z);
            accA.w = fmaf(pA, ex2f(fmaf(l4A.w, LOG2E, w4.w)), accA.w);
            accB.x = fmaf(pB, ex2f(fmaf(l4B.x, LOG2E, w4.x)), accB.x);
            accB.y = fmaf(pB, ex2f(fmaf(l4B.y, LOG2E, w4.y)), accB.y);
            accB.z = fmaf(pB, ex2f(fmaf(l4B.z, LOG2E, w4.z)), accB.z);
            accB.w = fmaf(pB, ex2f(fmaf(l4B.w, LOG2E, w4.w)), accB.w);
        }

        // Sum over the 4 row-residue lanes sharing each k' group.
#pragma unroll
        for (int off = 8; off <= 16; off <<= 1) {
            accA.x += __shfl_xor_sync(FULL, accA.x, off);
            accA.y += __shfl_xor_sync(FULL, accA.y, off);
            accA.z += __shfl_xor_sync(FULL, accA.z, off);
            accA.w += __shfl_xor_sync(FULL, accA.w, off);
            accB.x += __shfl_xor_sync(FULL, accB.x, off);
            accB.y += __shfl_xor_sync(FULL, accB.y, off);
            accB.z += __shfl_xor_sync(FULL, accB.z, off);
            accB.w += __shfl_xor_sync(FULL, accB.w, off);
        }

        // Redistribute to lane = k' layout: lane j takes comp j&3 of lane j>>2.
        int src = lane >> 2;
        int c   = lane & 3;
        float rA0 = __shfl_sync(FULL, accA.x, src);
        float rA1 = __shfl_sync(FULL, accA.y, src);
        float rA2 = __shfl_sync(FULL, accA.z, src);
        float rA3 = __shfl_sync(FULL, accA.w, src);
        float rB0 = __shfl_sync(FULL, accB.x, src);
        float rB1 = __shfl_sync(FULL, accB.y, src);
        float rB2 = __shfl_sync(FULL, accB.z, src);
        float rB3 = __shfl_sync(FULL, accB.w, src);
        float vA = (c == 0) ? rA0 : (c == 1) ? rA1 : (c == 2) ? rA2 : rA3;
        float vB = (c == 0) ? rB0 : (c == 1) ? rB1 : (c == 2) ? rB2 : rB3;

        aA = fmaf(lg2f(vA), LN2, mxA);
        aB = fmaf(lg2f(vB), LN2, mxB);
    }

    // Final logsumexp across lanes.
    float mA = aA, mB = aB;
#pragma unroll
    for (int off = 16; off; off >>= 1) {
        mA = fmaxf(mA, __shfl_xor_sync(FULL, mA, off));
        mB = fmaxf(mB, __shfl_xor_sync(FULL, mB, off));
    }
    float eA = ex2f((aA - mA) * LOG2E);
    float eB = ex2f((aB - mB) * LOG2E);
#pragma unroll
    for (int off = 16; off; off >>= 1) {
        eA += __shfl_xor_sync(FULL, eA, off);
        eB += __shfl_xor_sync(FULL, eB, off);
    }
    if (lane == 0) {
        out[n0]     = fmaf(lg2f(eA), LN2, mA);
        out[n0 + 1] = fmaf(lg2f(eB), LN2, mB);
    }
}

// ---------------------------------------------------------------------------
// Launch contract
// ---------------------------------------------------------------------------
extern "C" void kernel_launch(void* const* d_in, const int* in_sizes, int n_in,
                              void* d_out, int out_size) {
    const float* L   = (const float*)d_in[0];   // [8192, 32, 32, 32]
    const float* wk0 = (const float*)d_in[1];   // [1, 32]
    const float* W   = (const float*)d_in[2];   // [32, 32, 32]
    float* out = (float*)d_out;                 // [8192]

    (void)in_sizes; (void)n_in; (void)out_size;

    tt_prep_kernel<<<1, 1024>>>(W, wk0);
    // 8192 samples / 2 per warp / 8 warps per CTA = 512 CTAs
    tt_main_kernel<<<512, 256>>>(L, out);
}

// round 4
// speedup vs baseline: 1.2166x; 1.0111x over previous
#include <cuda_runtime.h>
#include <math.h>

#define FULL 0xffffffffu
#define LOG2E 1.4426950408889634f
#define LN2   0.6931471805599453f

// Precomputed log_softmax(W_m, axis=0) * LOG2E  [32,32,32]
// g_a0b: a0 in log2 units, blocked lane layout: lane i holds k' = 4(i%8)+(i>>3)
__device__ float g_wl2[32 * 32 * 32];
__device__ float g_a0b[32];

__device__ __forceinline__ float ex2f(float x) {
    float y; asm("ex2.approx.f32 %0, %1;" : "=f"(y) : "f"(x)); return y;
}
__device__ __forceinline__ float lg2f(float x) {
    float y; asm("lg2.approx.f32 %0, %1;" : "=f"(y) : "f"(x)); return y;
}
__device__ __forceinline__ float4 ldcs4(const float4* p) {
    float4 v;
    asm volatile("ld.global.cs.v4.f32 {%0,%1,%2,%3}, [%4];"
                 : "=f"(v.x), "=f"(v.y), "=f"(v.z), "=f"(v.w) : "l"(p));
    return v;
}

// ---------------------------------------------------------------------------
// Prep: thread t = (m, k') computes log_softmax over k of W[m, k, k'] (axis=0),
// scaled by LOG2E. Threads 0..31 also compute a0 (log2 units, blocked layout).
// ---------------------------------------------------------------------------
__global__ void tt_prep_kernel(const float* __restrict__ W,
                               const float* __restrict__ wk0) {
    int t = threadIdx.x;
    int m = t >> 5, kp = t & 31;

    float v[32];
    float mx = -INFINITY;
#pragma unroll
    for (int k = 0; k < 32; k++) {
        v[k] = W[m * 1024 + k * 32 + kp];
        mx = fmaxf(mx, v[k]);
    }
    float s = 0.f;
#pragma unroll
    for (int k = 0; k < 32; k++) s += expf(v[k] - mx);
    float lse = mx + logf(s);
#pragma unroll
    for (int k = 0; k < 32; k++)
        g_wl2[m * 1024 + k * 32 + kp] = (v[k] - lse) * LOG2E;

    if (t < 32) {
        float m2 = -INFINITY;
#pragma unroll
        for (int k = 0; k < 32; k++) m2 = fmaxf(m2, wk0[k]);
        float s2 = 0.f;
#pragma unroll
        for (int k = 0; k < 32; k++) s2 += expf(wk0[k] - m2);
        float lse0 = m2 + logf(s2);
        int kp0 = 4 * (t & 7) + (t >> 3);   // blocked layout
        g_a0b[t] = (wk0[kp0] - lse0) * LOG2E;
    }
}

// ---------------------------------------------------------------------------
// Main: 4 warps/CTA, each warp handles 2 samples (A, B), all loads float4.
// State b (= a * LOG2E) stays in BLOCKED lane layout the whole time:
//   lane i holds k' = 4(i%8) + (i>>3).
// Per m-step, iteration blk: lane i loads rows 4*blk+(i>>3), k' cols 4(i%8)..+3.
// Row factor for row k = 4*blk + rsub comes from lane (lane&24)|blk — a single
// shuffle, no transpose. Stability ref = lane 0's b (bounded exponents, exact
// result unchanged up to fp rounding).
// ---------------------------------------------------------------------------
__global__ void __launch_bounds__(128, 8)
tt_main_kernel(const float* __restrict__ L, float* __restrict__ out) {
    const int warp = threadIdx.x >> 5;
    const int lane = threadIdx.x & 31;
    const int n0 = (blockIdx.x * 4 + warp) * 2;
    const int rsub = lane >> 3;
    const int srcbase = lane & 24;

    const float4* LA = (const float4*)L + (size_t)n0 * 8192 + lane;
    const float4* LB = LA + 8192;
    const float4* W4 = (const float4*)g_wl2 + lane;

    float bA = g_a0b[lane];   // log2 domain, blocked layout
    float bB = bA;

#pragma unroll 1
    for (int m = 0; m < 32; m++) {
        const float refA = __shfl_sync(FULL, bA, 0);
        const float refB = __shfl_sync(FULL, bB, 0);

        const float4* lA = LA + m * 256;
        const float4* lB = LB + m * 256;
        const float4* w  = W4 + m * 256;

        float4 accA = make_float4(0.f, 0.f, 0.f, 0.f);
        float4 accB = make_float4(0.f, 0.f, 0.f, 0.f);

#pragma unroll
        for (int blk = 0; blk < 8; blk++) {
            float4 w4  = __ldg(w + blk * 32);
            float4 l4A = ldcs4(lA + blk * 32);
            float4 l4B = ldcs4(lB + blk * 32);
            float pA = ex2f(__shfl_sync(FULL, bA, srcbase | blk) - refA);
            float pB = ex2f(__shfl_sync(FULL, bB, srcbase | blk) - refB);

            accA.x = fmaf(pA, ex2f(fmaf(l4A.x, LOG2E, w4.x)), accA.x);
            accA.y = fmaf(pA, ex2f(fmaf(l4A.y, LOG2E, w4.y)), accA.y);
            accA.z = fmaf(pA, ex2f(fmaf(l4A.z, LOG2E, w4.z)), accA.z);
            accA.w = fmaf(pA, ex2f(fmaf(l4A.w, LOG2E, w4.w)), accA.w);
            accB.x = fmaf(pB, ex2f(fmaf(l4B.x, LOG2E, w4.x)), accB.x);
            accB.y = fmaf(pB, ex2f(fmaf(l4B.y, LOG2E, w4.y)), accB.y);
            accB.z = fmaf(pB, ex2f(fmaf(l4B.z, LOG2E, w4.z)), accB.z);
            accB.w = fmaf(pB, ex2f(fmaf(l4B.w, LOG2E, w4.w)), accB.w);
        }

        // Sum over the 4 row-residue lanes sharing each k' group.
#pragma unroll
        for (int off = 8; off <= 16; off <<= 1) {
            accA.x += __shfl_xor_sync(FULL, accA.x, off);
            accA.y += __shfl_xor_sync(FULL, accA.y, off);
            accA.z += __shfl_xor_sync(FULL, accA.z, off);
            accA.w += __shfl_xor_sync(FULL, accA.w, off);
            accB.x += __shfl_xor_sync(FULL, accB.x, off);
            accB.y += __shfl_xor_sync(FULL, accB.y, off);
            accB.z += __shfl_xor_sync(FULL, accB.z, off);
            accB.w += __shfl_xor_sync(FULL, accB.w, off);
        }

        // Stay in blocked layout: this lane keeps component rsub (k' = 4(i%8)+rsub).
        float vA = (rsub & 2) ? ((rsub & 1) ? accA.w : accA.z)
                              : ((rsub & 1) ? accA.y : accA.x);
        float vB = (rsub & 2) ? ((rsub & 1) ? accB.w : accB.z)
                              : ((rsub & 1) ? accB.y : accB.x);

        bA = lg2f(vA) + refA;
        bB = lg2f(vB) + refB;
    }

    // Final logsumexp across lanes (layout is a permutation — invariant).
    float mA = bA, mB = bB;
#pragma unroll
    for (int off = 16; off; off >>= 1) {
        mA = fmaxf(mA, __shfl_xor_sync(FULL, mA, off));
        mB = fmaxf(mB, __shfl_xor_sync(FULL, mB, off));
    }
    float eA = ex2f(bA - mA);
    float eB = ex2f(bB - mB);
#pragma unroll
    for (int off = 16; off; off >>= 1) {
        eA += __shfl_xor_sync(FULL, eA, off);
        eB += __shfl_xor_sync(FULL, eB, off);
    }
    if (lane == 0) {
        out[n0]     = (mA + lg2f(eA)) * LN2;
        out[n0 + 1] = (mB + lg2f(eB)) * LN2;
    }
}

// ---------------------------------------------------------------------------
// Launch contract
// ---------------------------------------------------------------------------
extern "C" void kernel_launch(void* const* d_in, const int* in_sizes, int n_in,
                              void* d_out, int out_size) {
    const float* L   = (const float*)d_in[0];   // [8192, 32, 32, 32]
    const float* wk0 = (const float*)d_in[1];   // [1, 32]
    const float* W   = (const float*)d_in[2];   // [32, 32, 32]
    float* out = (float*)d_out;                 // [8192]

    (void)in_sizes; (void)n_in; (void)out_size;

    tt_prep_kernel<<<1, 1024>>>(W, wk0);
    // 8192 samples / 2 per warp / 4 warps per CTA = 1024 CTAs (occ 8/SM, 1 wave)
    tt_main_kernel<<<1024, 128>>>(L, out);
}